// round 1
// baseline (speedup 1.0000x reference)
#include <cuda_runtime.h>
#include <math.h>
#include <cstdint>

#define NTOK 8192      // B*N = 8*1024
#define DIMC 768
#define FC1OUT 5376
#define MLPH 3072
#define QKVD 2304
#define FC2IN 3840
#define FC2OUT 1536

// ---------------- scratch (device globals; no allocation allowed) ----------------
__device__ float g_probsT[4 * NTOK];            // (B,E,N) layout: (b*4+e)*1024+n
__device__ float g_gate[4 * NTOK];              // gate if selected else 0
__device__ unsigned char g_sel[4 * NTOK];       // 0/1
__device__ float g_cS[NTOK * 8];                // per token: c0..c3, S0..S3
__device__ float g_yp[NTOK * DIMC];             // LN(x) * c_seg  (fc1 input)
__device__ float g_y2[NTOK * FC2IN];            // [gelu(mlp) | attn_out]  (fc2 input)
__device__ float g_qkv[NTOK * QKVD];            // raw qkv from fc1
__device__ float g_z[NTOK * FC2OUT];            // fc2 output (scaled)

// ---------------- K1: router logits + softmax ----------------
// one warp per token
__global__ __launch_bounds__(256) void router_kernel(const float* __restrict__ x,
                                                     const float* __restrict__ wr) {
    int warp = (blockIdx.x * blockDim.x + threadIdx.x) >> 5;
    int lane = threadIdx.x & 31;
    if (warp >= NTOK) return;
    const float* xr = x + warp * DIMC;
    float acc0 = 0.f, acc1 = 0.f, acc2 = 0.f, acc3 = 0.f;
    for (int d = lane; d < DIMC; d += 32) {
        float xv = xr[d];
        acc0 += xv * wr[0 * DIMC + d];
        acc1 += xv * wr[1 * DIMC + d];
        acc2 += xv * wr[2 * DIMC + d];
        acc3 += xv * wr[3 * DIMC + d];
    }
    #pragma unroll
    for (int o = 16; o; o >>= 1) {
        acc0 += __shfl_down_sync(0xffffffffu, acc0, o);
        acc1 += __shfl_down_sync(0xffffffffu, acc1, o);
        acc2 += __shfl_down_sync(0xffffffffu, acc2, o);
        acc3 += __shfl_down_sync(0xffffffffu, acc3, o);
    }
    if (lane == 0) {
        float mx = fmaxf(fmaxf(acc0, acc1), fmaxf(acc2, acc3));
        float p0 = expf(acc0 - mx), p1 = expf(acc1 - mx), p2 = expf(acc2 - mx), p3 = expf(acc3 - mx);
        float inv = 1.f / (p0 + p1 + p2 + p3);
        int b = warp >> 10, n = warp & 1023;
        g_probsT[(b * 4 + 0) * 1024 + n] = p0 * inv;
        g_probsT[(b * 4 + 1) * 1024 + n] = p1 * inv;
        g_probsT[(b * 4 + 2) * 1024 + n] = p2 * inv;
        g_probsT[(b * 4 + 3) * 1024 + n] = p3 * inv;
    }
}

// ---------------- K2: top-512 per (b,e) by rank counting ----------------
__global__ __launch_bounds__(1024) void topk_kernel() {
    __shared__ float sp[1024];
    int be = blockIdx.x;
    int i = threadIdx.x;
    float p = g_probsT[be * 1024 + i];
    sp[i] = p;
    __syncthreads();
    int cnt = 0;
    for (int j = 0; j < 1024; j++) {
        float q = sp[j];
        cnt += (q > p) || (q == p && j < i);
    }
    bool sel = cnt < 512;
    g_gate[be * 1024 + i] = sel ? p : 0.f;
    g_sel[be * 1024 + i] = sel ? 1 : 0;
}

// ---------------- K3: per-token suffix counts c_k and gate sums S_k ----------------
__global__ void stats_kernel() {
    int m = blockIdx.x * blockDim.x + threadIdx.x;
    if (m >= NTOK) return;
    int b = m >> 10, n = m & 1023;
    float csum = 0.f, ssum = 0.f;
    float c[4], S[4];
    #pragma unroll
    for (int e = 3; e >= 0; e--) {
        csum += (float)g_sel[(b * 4 + e) * 1024 + n];
        ssum += g_gate[(b * 4 + e) * 1024 + n];
        c[e] = csum;
        S[e] = ssum;
    }
    #pragma unroll
    for (int k = 0; k < 4; k++) {
        g_cS[m * 8 + k] = c[k];
        g_cS[m * 8 + 4 + k] = S[k];
    }
}

// ---------------- K4: LayerNorm * gamma + beta, scaled by c_seg(d) ----------------
__global__ __launch_bounds__(256) void ln_kernel(const float* __restrict__ x,
                                                 const float* __restrict__ gamma,
                                                 const float* __restrict__ beta) {
    int m = blockIdx.x;
    const float* xr = x + m * DIMC;
    float s = 0.f, s2 = 0.f;
    for (int d = threadIdx.x; d < DIMC; d += 256) {
        float v = xr[d];
        s += v;
        s2 += v * v;
    }
    #pragma unroll
    for (int o = 16; o; o >>= 1) {
        s += __shfl_down_sync(0xffffffffu, s, o);
        s2 += __shfl_down_sync(0xffffffffu, s2, o);
    }
    __shared__ float sh[16];
    int w = threadIdx.x >> 5, lane = threadIdx.x & 31;
    if (lane == 0) { sh[w] = s; sh[8 + w] = s2; }
    __syncthreads();
    if (threadIdx.x == 0) {
        float ts = 0.f, ts2 = 0.f;
        #pragma unroll
        for (int i = 0; i < 8; i++) { ts += sh[i]; ts2 += sh[8 + i]; }
        float mu = ts * (1.f / 768.f);
        float var = ts2 * (1.f / 768.f) - mu * mu;
        sh[0] = mu;
        sh[1] = rsqrtf(var + 1e-6f);
    }
    __syncthreads();
    float mu = sh[0], rstd = sh[1];
    float c0 = g_cS[m * 8 + 0], c1 = g_cS[m * 8 + 1], c2 = g_cS[m * 8 + 2], c3 = g_cS[m * 8 + 3];
    for (int d = threadIdx.x; d < DIMC; d += 256) {
        float c = (d < 96) ? c0 : (d < 192) ? c1 : (d < 384) ? c2 : c3;
        g_yp[m * DIMC + d] = ((xr[d] - mu) * rstd * gamma[d] + beta[d]) * c;
    }
}

// ---------------- GEMM: C[m,n] = sum_k A[m,k]*W[n,k], fused epilogues ----------------
// MODE 1: A=g_yp (K=768), N=5376.  out: f<3072 -> gelu -> g_y2[:, :3072]; else -> g_qkv
// MODE 2: A=g_y2 (K=3840), N=1536. out: (acc+b2[o]) * S_seg(o%768) -> g_z
template <int MODE>
__global__ __launch_bounds__(256) void gemm_kernel(const float* __restrict__ W,
                                                   const float* __restrict__ bias) {
    constexpr int KDIM = (MODE == 1) ? DIMC : FC2IN;
    const float* __restrict__ A = (MODE == 1) ? g_yp : g_y2;

    __shared__ float As[16][128];
    __shared__ float Bs[16][128];

    int tid = threadIdx.x;
    int m0 = blockIdx.y * 128;
    int n0 = blockIdx.x * 128;

    int lrow = tid >> 1;
    int lk = (tid & 1) * 8;
    const float* Ap = A + (m0 + lrow) * KDIM + lk;
    const float* Bp = W + (n0 + lrow) * KDIM + lk;

    float4 ra0 = *(const float4*)(Ap);
    float4 ra1 = *(const float4*)(Ap + 4);
    float4 rb0 = *(const float4*)(Bp);
    float4 rb1 = *(const float4*)(Bp + 4);

    float acc[2][2][4][4];
    #pragma unroll
    for (int a = 0; a < 2; a++)
        #pragma unroll
        for (int b = 0; b < 2; b++)
            #pragma unroll
            for (int i = 0; i < 4; i++)
                #pragma unroll
                for (int j = 0; j < 4; j++) acc[a][b][i][j] = 0.f;

    int tx = tid & 15, ty = tid >> 4;

    constexpr int NT = KDIM / 16;
    for (int kt = 0; kt < NT; kt++) {
        As[lk + 0][lrow] = ra0.x; As[lk + 1][lrow] = ra0.y;
        As[lk + 2][lrow] = ra0.z; As[lk + 3][lrow] = ra0.w;
        As[lk + 4][lrow] = ra1.x; As[lk + 5][lrow] = ra1.y;
        As[lk + 6][lrow] = ra1.z; As[lk + 7][lrow] = ra1.w;
        Bs[lk + 0][lrow] = rb0.x; Bs[lk + 1][lrow] = rb0.y;
        Bs[lk + 2][lrow] = rb0.z; Bs[lk + 3][lrow] = rb0.w;
        Bs[lk + 4][lrow] = rb1.x; Bs[lk + 5][lrow] = rb1.y;
        Bs[lk + 6][lrow] = rb1.z; Bs[lk + 7][lrow] = rb1.w;
        __syncthreads();
        if (kt + 1 < NT) {
            const float* An = Ap + (kt + 1) * 16;
            const float* Bn = Bp + (kt + 1) * 16;
            ra0 = *(const float4*)(An);
            ra1 = *(const float4*)(An + 4);
            rb0 = *(const float4*)(Bn);
            rb1 = *(const float4*)(Bn + 4);
        }
        #pragma unroll
        for (int k = 0; k < 16; k++) {
            float a0[4], a1[4], b0[4], b1v[4];
            *(float4*)a0 = *(const float4*)&As[k][ty * 4];
            *(float4*)a1 = *(const float4*)&As[k][64 + ty * 4];
            *(float4*)b0 = *(const float4*)&Bs[k][tx * 4];
            *(float4*)b1v = *(const float4*)&Bs[k][64 + tx * 4];
            #pragma unroll
            for (int i = 0; i < 4; i++)
                #pragma unroll
                for (int j = 0; j < 4; j++) {
                    acc[0][0][i][j] += a0[i] * b0[j];
                    acc[0][1][i][j] += a0[i] * b1v[j];
                    acc[1][0][i][j] += a1[i] * b0[j];
                    acc[1][1][i][j] += a1[i] * b1v[j];
                }
        }
        __syncthreads();
    }

    #pragma unroll
    for (int ri = 0; ri < 2; ri++)
        #pragma unroll
        for (int i = 0; i < 4; i++) {
            int m = m0 + ri * 64 + ty * 4 + i;
            if (MODE == 1) {
                float c0 = g_cS[m * 8];
                #pragma unroll
                for (int rj = 0; rj < 2; rj++)
                    #pragma unroll
                    for (int j = 0; j < 4; j++) {
                        int f = n0 + rj * 64 + tx * 4 + j;
                        float v = acc[ri][rj][i][j] + c0 * bias[f];
                        if (f < MLPH) {
                            g_y2[m * FC2IN + f] = 0.5f * v * (1.f + erff(v * 0.70710678118654752f));
                        } else {
                            g_qkv[m * QKVD + (f - MLPH)] = v;
                        }
                    }
            } else {
                #pragma unroll
                for (int rj = 0; rj < 2; rj++)
                    #pragma unroll
                    for (int j = 0; j < 4; j++) {
                        int o = n0 + rj * 64 + tx * 4 + j;
                        int op = (o >= 768) ? (o - 768) : o;
                        int seg = (op >= 384) ? 3 : (op >= 192) ? 2 : (op >= 96) ? 1 : 0;
                        g_z[m * FC2OUT + o] = (acc[ri][rj][i][j] + bias[o]) * g_cS[m * 8 + 4 + seg];
                    }
            }
        }
}

// ---------------- K6: attention (streaming softmax, q/acc in registers) ----------------
// grid: (B*H, N/128), block: 128 threads (one q row each). K/V tiles of 64 rows in smem.
__global__ __launch_bounds__(128) void attn_kernel() {
    __shared__ float Ks[64][64];
    __shared__ float Vs[64][64];
    int bh = blockIdx.x;
    int b = bh / 12, h = bh % 12;
    int qi = blockIdx.y * 128 + threadIdx.x;
    int m = b * 1024 + qi;
    const float scale = 0.125f;  // 64^-0.5

    float q[64];
    const float* qp = g_qkv + m * QKVD + h * 64;
    #pragma unroll
    for (int d = 0; d < 64; d += 4) {
        float4 v = *(const float4*)(qp + d);
        q[d] = v.x * scale; q[d + 1] = v.y * scale; q[d + 2] = v.z * scale; q[d + 3] = v.w * scale;
    }
    float accv[64];
    #pragma unroll
    for (int d = 0; d < 64; d++) accv[d] = 0.f;
    float mx = -1e30f, l = 0.f;

    for (int kt = 0; kt < 16; kt++) {
        __syncthreads();
        int r = threadIdx.x >> 1;
        int cbase = (threadIdx.x & 1) * 32;
        int km = b * 1024 + kt * 64 + r;
        const float* kp = g_qkv + km * QKVD + 768 + h * 64 + cbase;
        const float* vp = kp + 768;
        #pragma unroll
        for (int d4 = 0; d4 < 32; d4 += 4) {
            *(float4*)&Ks[r][cbase + d4] = *(const float4*)(kp + d4);
            *(float4*)&Vs[r][cbase + d4] = *(const float4*)(vp + d4);
        }
        __syncthreads();
        for (int j = 0; j < 64; j++) {
            float s = 0.f;
            #pragma unroll
            for (int d = 0; d < 64; d++) s += q[d] * Ks[j][d];
            if (s <= mx) {
                float p = __expf(s - mx);
                l += p;
                #pragma unroll
                for (int d = 0; d < 64; d++) accv[d] += p * Vs[j][d];
            } else {
                float corr = __expf(mx - s);
                l = l * corr + 1.f;
                #pragma unroll
                for (int d = 0; d < 64; d++) accv[d] = accv[d] * corr + Vs[j][d];
                mx = s;
            }
        }
    }
    float inv = 1.f / l;
    float* op = g_y2 + m * FC2IN + MLPH + h * 64;
    #pragma unroll
    for (int d = 0; d < 64; d++) op[d] = accv[d] * inv;
}

// ---------------- K8: residual combine ----------------
__global__ void final_kernel(const float* __restrict__ x, float* __restrict__ out) {
    int i = blockIdx.x * blockDim.x + threadIdx.x;
    if (i >= NTOK * DIMC) return;
    int m = i / DIMC, c = i - m * DIMC;
    out[i] = x[i] + g_z[m * FC2OUT + c] + g_z[m * FC2OUT + 768 + c];
}

// ---------------- launch ----------------
extern "C" void kernel_launch(void* const* d_in, const int* in_sizes, int n_in,
                              void* d_out, int out_size) {
    const float* x = (const float*)d_in[0];
    const float* wr = (const float*)d_in[1];
    const float* gamma = (const float*)d_in[2];
    const float* beta = (const float*)d_in[3];
    const float* w1 = (const float*)d_in[4];
    const float* b1 = (const float*)d_in[5];
    const float* w2 = (const float*)d_in[6];
    const float* b2 = (const float*)d_in[7];
    float* out = (float*)d_out;

    router_kernel<<<NTOK / 8, 256>>>(x, wr);
    topk_kernel<<<32, 1024>>>();
    stats_kernel<<<NTOK / 256, 256>>>();
    ln_kernel<<<NTOK, 256>>>(x, gamma, beta);
    gemm_kernel<1><<<dim3(FC1OUT / 128, NTOK / 128), 256>>>(w1, b1);
    attn_kernel<<<dim3(96, 8), 128>>>();
    gemm_kernel<2><<<dim3(FC2OUT / 128, NTOK / 128), 256>>>(w2, b2);
    final_kernel<<<(NTOK * DIMC + 255) / 256, 256>>>(x, out);
}

// round 3
// speedup vs baseline: 2.1891x; 2.1891x over previous
#include <cuda_runtime.h>
#include <cuda_fp16.h>
#include <math.h>
#include <cstdint>

#define NTOK 8192      // B*N = 8*1024
#define DIMC 768
#define FC1OUT 5376
#define MLPH 3072
#define QKVD 2304
#define FC2IN 3840
#define FC2OUT 1536

// ---------------- scratch (device globals; no allocation allowed) ----------------
__device__ float g_probsT[4 * NTOK];
__device__ float g_gate[4 * NTOK];
__device__ unsigned char g_sel[4 * NTOK];
__device__ float g_cS[NTOK * 8];                 // c0..c3, S0..S3 per token
__device__ __half g_yph[NTOK * DIMC];            // fp16(LN(x) * c_seg)  (fc1 A)
__device__ __half g_y2h[NTOK * FC2IN];           // fp16([gelu(mlp) | attn_out]) (fc2 A)
__device__ float g_qkv[NTOK * QKVD];             // fp32 qkv from fc1 (attn input)
__device__ float g_z[NTOK * FC2OUT];
__device__ __half g_w1h[FC1OUT * DIMC];          // fp16 weights
__device__ __half g_w2h[FC2OUT * FC2IN];

// ---------------- K1: router logits + softmax ----------------
__global__ __launch_bounds__(256) void router_kernel(const float* __restrict__ x,
                                                     const float* __restrict__ wr) {
    int warp = (blockIdx.x * blockDim.x + threadIdx.x) >> 5;
    int lane = threadIdx.x & 31;
    if (warp >= NTOK) return;
    const float* xr = x + warp * DIMC;
    float acc0 = 0.f, acc1 = 0.f, acc2 = 0.f, acc3 = 0.f;
    for (int d = lane; d < DIMC; d += 32) {
        float xv = xr[d];
        acc0 += xv * wr[0 * DIMC + d];
        acc1 += xv * wr[1 * DIMC + d];
        acc2 += xv * wr[2 * DIMC + d];
        acc3 += xv * wr[3 * DIMC + d];
    }
    #pragma unroll
    for (int o = 16; o; o >>= 1) {
        acc0 += __shfl_down_sync(0xffffffffu, acc0, o);
        acc1 += __shfl_down_sync(0xffffffffu, acc1, o);
        acc2 += __shfl_down_sync(0xffffffffu, acc2, o);
        acc3 += __shfl_down_sync(0xffffffffu, acc3, o);
    }
    if (lane == 0) {
        float mx = fmaxf(fmaxf(acc0, acc1), fmaxf(acc2, acc3));
        float p0 = expf(acc0 - mx), p1 = expf(acc1 - mx), p2 = expf(acc2 - mx), p3 = expf(acc3 - mx);
        float inv = 1.f / (p0 + p1 + p2 + p3);
        int b = warp >> 10, n = warp & 1023;
        g_probsT[(b * 4 + 0) * 1024 + n] = p0 * inv;
        g_probsT[(b * 4 + 1) * 1024 + n] = p1 * inv;
        g_probsT[(b * 4 + 2) * 1024 + n] = p2 * inv;
        g_probsT[(b * 4 + 3) * 1024 + n] = p3 * inv;
    }
}

// ---------------- K2: top-512 per (b,e) by rank counting ----------------
__global__ __launch_bounds__(1024) void topk_kernel() {
    __shared__ float sp[1024];
    int be = blockIdx.x;
    int i = threadIdx.x;
    float p = g_probsT[be * 1024 + i];
    sp[i] = p;
    __syncthreads();
    int cnt = 0;
    for (int j = 0; j < 1024; j++) {
        float q = sp[j];
        cnt += (q > p) || (q == p && j < i);
    }
    bool sel = cnt < 512;
    g_gate[be * 1024 + i] = sel ? p : 0.f;
    g_sel[be * 1024 + i] = sel ? 1 : 0;
}

// ---------------- K3: suffix counts / gate sums ----------------
__global__ void stats_kernel() {
    int m = blockIdx.x * blockDim.x + threadIdx.x;
    if (m >= NTOK) return;
    int b = m >> 10, n = m & 1023;
    float csum = 0.f, ssum = 0.f;
    float c[4], S[4];
    #pragma unroll
    for (int e = 3; e >= 0; e--) {
        csum += (float)g_sel[(b * 4 + e) * 1024 + n];
        ssum += g_gate[(b * 4 + e) * 1024 + n];
        c[e] = csum;
        S[e] = ssum;
    }
    #pragma unroll
    for (int k = 0; k < 4; k++) {
        g_cS[m * 8 + k] = c[k];
        g_cS[m * 8 + 4 + k] = S[k];
    }
}

// ---------------- K4: LayerNorm * c_seg -> fp16 ----------------
__global__ __launch_bounds__(256) void ln_kernel(const float* __restrict__ x,
                                                 const float* __restrict__ gamma,
                                                 const float* __restrict__ beta) {
    int m = blockIdx.x;
    const float* xr = x + m * DIMC;
    float s = 0.f, s2 = 0.f;
    for (int d = threadIdx.x; d < DIMC; d += 256) {
        float v = xr[d];
        s += v;
        s2 += v * v;
    }
    #pragma unroll
    for (int o = 16; o; o >>= 1) {
        s += __shfl_down_sync(0xffffffffu, s, o);
        s2 += __shfl_down_sync(0xffffffffu, s2, o);
    }
    __shared__ float sh[16];
    int w = threadIdx.x >> 5, lane = threadIdx.x & 31;
    if (lane == 0) { sh[w] = s; sh[8 + w] = s2; }
    __syncthreads();
    if (threadIdx.x == 0) {
        float ts = 0.f, ts2 = 0.f;
        #pragma unroll
        for (int i = 0; i < 8; i++) { ts += sh[i]; ts2 += sh[8 + i]; }
        float mu = ts * (1.f / 768.f);
        float var = ts2 * (1.f / 768.f) - mu * mu;
        sh[0] = mu;
        sh[1] = rsqrtf(var + 1e-6f);
    }
    __syncthreads();
    float mu = sh[0], rstd = sh[1];
    float c0 = g_cS[m * 8 + 0], c1 = g_cS[m * 8 + 1], c2 = g_cS[m * 8 + 2], c3 = g_cS[m * 8 + 3];
    for (int d = threadIdx.x; d < DIMC; d += 256) {
        float c = (d < 96) ? c0 : (d < 192) ? c1 : (d < 384) ? c2 : c3;
        g_yph[m * DIMC + d] = __float2half_rn(((xr[d] - mu) * rstd * gamma[d] + beta[d]) * c);
    }
}

// ---------------- fp32 -> fp16 weight conversion ----------------
__global__ void h_cvt_kernel(const float* __restrict__ src, __half* __restrict__ dst, int n4) {
    int i = blockIdx.x * blockDim.x + threadIdx.x;
    if (i >= n4) return;
    float4 v = ((const float4*)src)[i];
    __half2 h01 = __floats2half2_rn(v.x, v.y);
    __half2 h23 = __floats2half2_rn(v.z, v.w);
    ((__half2*)dst)[i * 2] = h01;
    ((__half2*)dst)[i * 2 + 1] = h23;
}

// ================= HMMA helpers (sm_80+, family-portable) =================
__device__ __forceinline__ void ldsm_x4(uint32_t& r0, uint32_t& r1, uint32_t& r2, uint32_t& r3, uint32_t addr) {
    asm volatile("ldmatrix.sync.aligned.m8n8.x4.shared.b16 {%0,%1,%2,%3}, [%4];"
                 : "=r"(r0), "=r"(r1), "=r"(r2), "=r"(r3) : "r"(addr));
}
__device__ __forceinline__ void ldsm_x2(uint32_t& r0, uint32_t& r1, uint32_t addr) {
    asm volatile("ldmatrix.sync.aligned.m8n8.x2.shared.b16 {%0,%1}, [%2];"
                 : "=r"(r0), "=r"(r1) : "r"(addr));
}
__device__ __forceinline__ void mma16816(float* c, const uint32_t* a, const uint32_t* b) {
    asm volatile("mma.sync.aligned.m16n8k16.row.col.f32.f16.f16.f32 "
                 "{%0,%1,%2,%3}, {%4,%5,%6,%7}, {%8,%9}, {%0,%1,%2,%3};"
                 : "+f"(c[0]), "+f"(c[1]), "+f"(c[2]), "+f"(c[3])
                 : "r"(a[0]), "r"(a[1]), "r"(a[2]), "r"(a[3]), "r"(b[0]), "r"(b[1]));
}

// ================ HMMA GEMM: D[m,n] = sum_k A[m,k] * W[n,k] ================
// tile M=128 N=128 Ktile=32, 256 threads (8 warps in 2x4), per-warp 64x32 via 4x4 m16n8k16
// MODE 1: A=g_yph K=768,  W=g_w1h; epilogue: f<3072 -> gelu -> g_y2h; else -> g_qkv (fp32); bias c0*b1
// MODE 2: A=g_y2h K=3840, W=g_w2h; epilogue: (acc+b2[o])*S_seg(o%768) -> g_z
template <int MODE>
__global__ __launch_bounds__(256) void gemm_mma(const __half* __restrict__ Wh,
                                                const float* __restrict__ bias) {
    constexpr int KDIM = (MODE == 1) ? DIMC : FC2IN;
    constexpr int NT = KDIM / 32;
    const __half* __restrict__ A = (MODE == 1) ? (const __half*)g_yph : (const __half*)g_y2h;

    __shared__ __half As[2][128][40];   // 40-half stride: 16B-aligned rows, ldmatrix conflict-free
    __shared__ __half Bs[2][128][40];

    int tid = threadIdx.x, wid = tid >> 5, lane = tid & 31;
    int m0 = blockIdx.y * 128, n0 = blockIdx.x * 128;
    int wm = wid & 1, wn = wid >> 1;

    int lrow = tid >> 1, lcol = (tid & 1) * 16;
    const __half* Ag = A + (m0 + lrow) * KDIM + lcol;
    const __half* Bg = Wh + (n0 + lrow) * KDIM + lcol;

    uint4 pa0 = *(const uint4*)Ag;
    uint4 pa1 = *(const uint4*)(Ag + 8);
    uint4 pb0 = *(const uint4*)Bg;
    uint4 pb1 = *(const uint4*)(Bg + 8);

    float acc[4][4][4];
    #pragma unroll
    for (int i = 0; i < 4; i++)
        #pragma unroll
        for (int j = 0; j < 4; j++)
            #pragma unroll
            for (int t = 0; t < 4; t++) acc[i][j][t] = 0.f;

    uint32_t as_base = (uint32_t)__cvta_generic_to_shared(&As[0][0][0]);
    uint32_t bs_base = (uint32_t)__cvta_generic_to_shared(&Bs[0][0][0]);
    constexpr uint32_t BUFB = 128 * 40 * 2;

    for (int kt = 0; kt < NT; kt++) {
        int buf = kt & 1;
        *(uint4*)&As[buf][lrow][lcol] = pa0;
        *(uint4*)&As[buf][lrow][lcol + 8] = pa1;
        *(uint4*)&Bs[buf][lrow][lcol] = pb0;
        *(uint4*)&Bs[buf][lrow][lcol + 8] = pb1;
        __syncthreads();
        if (kt + 1 < NT) {
            const __half* an = Ag + (kt + 1) * 32;
            const __half* bn = Bg + (kt + 1) * 32;
            pa0 = *(const uint4*)an;
            pa1 = *(const uint4*)(an + 8);
            pb0 = *(const uint4*)bn;
            pb1 = *(const uint4*)(bn + 8);
        }
        uint32_t abase = as_base + buf * BUFB;
        uint32_t bbase = bs_base + buf * BUFB;
        #pragma unroll
        for (int ks = 0; ks < 2; ks++) {
            uint32_t af[4][4];
            #pragma unroll
            for (int i = 0; i < 4; i++) {
                uint32_t r = wm * 64 + i * 16 + (lane & 15);
                uint32_t c = ks * 16 + (lane >> 4) * 8;
                ldsm_x4(af[i][0], af[i][1], af[i][2], af[i][3], abase + (r * 40 + c) * 2);
            }
            uint32_t bf[4][2];
            #pragma unroll
            for (int j = 0; j < 4; j++) {
                uint32_t r = wn * 32 + j * 8 + (lane & 7);
                uint32_t c = ks * 16 + ((lane >> 3) & 1) * 8;
                ldsm_x2(bf[j][0], bf[j][1], bbase + (r * 40 + c) * 2);
            }
            #pragma unroll
            for (int i = 0; i < 4; i++)
                #pragma unroll
                for (int j = 0; j < 4; j++) mma16816(acc[i][j], af[i], bf[j]);
        }
    }

    // epilogue: c0,c1 -> row l/4, cols (l%4)*2,+1 ; c2,c3 -> row l/4+8
    #pragma unroll
    for (int i = 0; i < 4; i++) {
        int m_a = m0 + wm * 64 + i * 16 + (lane >> 2);
        int m_b = m_a + 8;
        if (MODE == 1) {
            float c0a = g_cS[m_a * 8], c0b = g_cS[m_b * 8];
            #pragma unroll
            for (int j = 0; j < 4; j++) {
                int f = n0 + wn * 32 + j * 8 + (lane & 3) * 2;
                float b0v = bias[f], b1v = bias[f + 1];
                float v0 = acc[i][j][0] + c0a * b0v;
                float v1 = acc[i][j][1] + c0a * b1v;
                float v2 = acc[i][j][2] + c0b * b0v;
                float v3 = acc[i][j][3] + c0b * b1v;
                if (f < MLPH) {
                    const float is2 = 0.70710678118654752f;
                    v0 = 0.5f * v0 * (1.f + erff(v0 * is2));
                    v1 = 0.5f * v1 * (1.f + erff(v1 * is2));
                    v2 = 0.5f * v2 * (1.f + erff(v2 * is2));
                    v3 = 0.5f * v3 * (1.f + erff(v3 * is2));
                    *(__half2*)&g_y2h[m_a * FC2IN + f] = __floats2half2_rn(v0, v1);
                    *(__half2*)&g_y2h[m_b * FC2IN + f] = __floats2half2_rn(v2, v3);
                } else {
                    *(float2*)&g_qkv[m_a * QKVD + (f - MLPH)] = make_float2(v0, v1);
                    *(float2*)&g_qkv[m_b * QKVD + (f - MLPH)] = make_float2(v2, v3);
                }
            }
        } else {
            #pragma unroll
            for (int j = 0; j < 4; j++) {
                int o = n0 + wn * 32 + j * 8 + (lane & 3) * 2;
                int op = (o >= 768) ? (o - 768) : o;
                int seg = (op >= 384) ? 3 : (op >= 192) ? 2 : (op >= 96) ? 1 : 0;
                float Sa = g_cS[m_a * 8 + 4 + seg], Sb = g_cS[m_b * 8 + 4 + seg];
                float b0v = bias[o], b1v = bias[o + 1];
                *(float2*)&g_z[m_a * FC2OUT + o] =
                    make_float2((acc[i][j][0] + b0v) * Sa, (acc[i][j][1] + b1v) * Sa);
                *(float2*)&g_z[m_b * FC2OUT + o] =
                    make_float2((acc[i][j][2] + b0v) * Sb, (acc[i][j][3] + b1v) * Sb);
            }
        }
    }
}

// ---------------- K6: attention (streaming softmax, fp32) ----------------
__global__ __launch_bounds__(128) void attn_kernel() {
    __shared__ float Ks[64][64];
    __shared__ float Vs[64][64];
    int bh = blockIdx.x;
    int b = bh / 12, h = bh % 12;
    int qi = blockIdx.y * 128 + threadIdx.x;
    int m = b * 1024 + qi;
    const float scale = 0.125f;

    float q[64];
    const float* qp = g_qkv + m * QKVD + h * 64;
    #pragma unroll
    for (int d = 0; d < 64; d += 4) {
        float4 v = *(const float4*)(qp + d);
        q[d] = v.x * scale; q[d + 1] = v.y * scale; q[d + 2] = v.z * scale; q[d + 3] = v.w * scale;
    }
    float accv[64];
    #pragma unroll
    for (int d = 0; d < 64; d++) accv[d] = 0.f;
    float mx = -1e30f, l = 0.f;

    for (int kt = 0; kt < 16; kt++) {
        __syncthreads();
        int r = threadIdx.x >> 1;
        int cbase = (threadIdx.x & 1) * 32;
        int km = b * 1024 + kt * 64 + r;
        const float* kp = g_qkv + km * QKVD + 768 + h * 64 + cbase;
        const float* vp = kp + 768;
        #pragma unroll
        for (int d4 = 0; d4 < 32; d4 += 4) {
            *(float4*)&Ks[r][cbase + d4] = *(const float4*)(kp + d4);
            *(float4*)&Vs[r][cbase + d4] = *(const float4*)(vp + d4);
        }
        __syncthreads();
        for (int j = 0; j < 64; j++) {
            float s = 0.f;
            #pragma unroll
            for (int d = 0; d < 64; d++) s += q[d] * Ks[j][d];
            if (s <= mx) {
                float p = __expf(s - mx);
                l += p;
                #pragma unroll
                for (int d = 0; d < 64; d++) accv[d] += p * Vs[j][d];
            } else {
                float corr = __expf(mx - s);
                l = l * corr + 1.f;
                #pragma unroll
                for (int d = 0; d < 64; d++) accv[d] = accv[d] * corr + Vs[j][d];
                mx = s;
            }
        }
    }
    float inv = 1.f / l;
    __half* op = g_y2h + m * FC2IN + MLPH + h * 64;
    #pragma unroll
    for (int d = 0; d < 64; d += 2) {
        *(__half2*)&op[d] = __floats2half2_rn(accv[d] * inv, accv[d + 1] * inv);
    }
}

// ---------------- K8: residual combine ----------------
__global__ void final_kernel(const float* __restrict__ x, float* __restrict__ out) {
    int i = blockIdx.x * blockDim.x + threadIdx.x;
    if (i >= NTOK * DIMC) return;
    int m = i / DIMC, c = i - m * DIMC;
    out[i] = x[i] + g_z[m * FC2OUT + c] + g_z[m * FC2OUT + 768 + c];
}

// ---------------- launch ----------------
extern "C" void kernel_launch(void* const* d_in, const int* in_sizes, int n_in,
                              void* d_out, int out_size) {
    const float* x = (const float*)d_in[0];
    const float* wr = (const float*)d_in[1];
    const float* gamma = (const float*)d_in[2];
    const float* beta = (const float*)d_in[3];
    const float* w1 = (const float*)d_in[4];
    const float* b1 = (const float*)d_in[5];
    const float* w2 = (const float*)d_in[6];
    const float* b2 = (const float*)d_in[7];
    float* out = (float*)d_out;

    __half* w1h; cudaGetSymbolAddress((void**)&w1h, g_w1h);
    __half* w2h; cudaGetSymbolAddress((void**)&w2h, g_w2h);

    router_kernel<<<NTOK / 8, 256>>>(x, wr);
    topk_kernel<<<32, 1024>>>();
    stats_kernel<<<NTOK / 256, 256>>>();
    ln_kernel<<<NTOK, 256>>>(x, gamma, beta);
    h_cvt_kernel<<<(FC1OUT * DIMC / 4 + 255) / 256, 256>>>(w1, w1h, FC1OUT * DIMC / 4);
    h_cvt_kernel<<<(FC2OUT * FC2IN / 4 + 255) / 256, 256>>>(w2, w2h, FC2OUT * FC2IN / 4);
    gemm_mma<1><<<dim3(FC1OUT / 128, NTOK / 128), 256>>>(w1h, b1);
    attn_kernel<<<dim3(96, 8), 128>>>();
    gemm_mma<2><<<dim3(FC2OUT / 128, NTOK / 128), 256>>>(w2h, b2);
    final_kernel<<<(NTOK * DIMC + 255) / 256, 256>>>(x, out);
}

// round 4
// speedup vs baseline: 4.9215x; 2.2482x over previous
#include <cuda_runtime.h>
#include <cuda_fp16.h>
#include <math.h>
#include <cstdint>

#define NTOK 8192      // B*N = 8*1024
#define DIMC 768
#define FC1OUT 5376
#define MLPH 3072
#define QKVD 2304
#define FC2IN 3840
#define FC2OUT 1536

// ---------------- scratch (device globals; no allocation allowed) ----------------
__device__ float g_probsT[4 * NTOK];
__device__ float g_gate[4 * NTOK];
__device__ unsigned char g_sel[4 * NTOK];
__device__ float g_cS[NTOK * 8];                 // c0..c3, S0..S3 per token
__device__ __half g_yph[NTOK * DIMC];            // fp16(LN(x) * c_seg)  (fc1 A)
__device__ __half g_y2h[NTOK * FC2IN];           // fp16([gelu(mlp) | attn_out]) (fc2 A)
__device__ __half g_qkvh[NTOK * QKVD];           // fp16 qkv (q pre-scaled by 0.125)
__device__ float g_z[NTOK * FC2OUT];
__device__ __half g_w1h[FC1OUT * DIMC];          // fp16 weights
__device__ __half g_w2h[FC2OUT * FC2IN];

// ---------------- K1: router logits + softmax ----------------
__global__ __launch_bounds__(256) void router_kernel(const float* __restrict__ x,
                                                     const float* __restrict__ wr) {
    int warp = (blockIdx.x * blockDim.x + threadIdx.x) >> 5;
    int lane = threadIdx.x & 31;
    if (warp >= NTOK) return;
    const float* xr = x + warp * DIMC;
    float acc0 = 0.f, acc1 = 0.f, acc2 = 0.f, acc3 = 0.f;
    for (int d = lane; d < DIMC; d += 32) {
        float xv = xr[d];
        acc0 += xv * wr[0 * DIMC + d];
        acc1 += xv * wr[1 * DIMC + d];
        acc2 += xv * wr[2 * DIMC + d];
        acc3 += xv * wr[3 * DIMC + d];
    }
    #pragma unroll
    for (int o = 16; o; o >>= 1) {
        acc0 += __shfl_down_sync(0xffffffffu, acc0, o);
        acc1 += __shfl_down_sync(0xffffffffu, acc1, o);
        acc2 += __shfl_down_sync(0xffffffffu, acc2, o);
        acc3 += __shfl_down_sync(0xffffffffu, acc3, o);
    }
    if (lane == 0) {
        float mx = fmaxf(fmaxf(acc0, acc1), fmaxf(acc2, acc3));
        float p0 = expf(acc0 - mx), p1 = expf(acc1 - mx), p2 = expf(acc2 - mx), p3 = expf(acc3 - mx);
        float inv = 1.f / (p0 + p1 + p2 + p3);
        int b = warp >> 10, n = warp & 1023;
        g_probsT[(b * 4 + 0) * 1024 + n] = p0 * inv;
        g_probsT[(b * 4 + 1) * 1024 + n] = p1 * inv;
        g_probsT[(b * 4 + 2) * 1024 + n] = p2 * inv;
        g_probsT[(b * 4 + 3) * 1024 + n] = p3 * inv;
    }
}

// ---------------- K2: top-512 per (b,e) by rank counting ----------------
__global__ __launch_bounds__(1024) void topk_kernel() {
    __shared__ float sp[1024];
    int be = blockIdx.x;
    int i = threadIdx.x;
    float p = g_probsT[be * 1024 + i];
    sp[i] = p;
    __syncthreads();
    int cnt = 0;
    for (int j = 0; j < 1024; j++) {
        float q = sp[j];
        cnt += (q > p) || (q == p && j < i);
    }
    bool sel = cnt < 512;
    g_gate[be * 1024 + i] = sel ? p : 0.f;
    g_sel[be * 1024 + i] = sel ? 1 : 0;
}

// ---------------- K3: suffix counts / gate sums ----------------
__global__ void stats_kernel() {
    int m = blockIdx.x * blockDim.x + threadIdx.x;
    if (m >= NTOK) return;
    int b = m >> 10, n = m & 1023;
    float csum = 0.f, ssum = 0.f;
    float c[4], S[4];
    #pragma unroll
    for (int e = 3; e >= 0; e--) {
        csum += (float)g_sel[(b * 4 + e) * 1024 + n];
        ssum += g_gate[(b * 4 + e) * 1024 + n];
        c[e] = csum;
        S[e] = ssum;
    }
    #pragma unroll
    for (int k = 0; k < 4; k++) {
        g_cS[m * 8 + k] = c[k];
        g_cS[m * 8 + 4 + k] = S[k];
    }
}

// ---------------- K4: LayerNorm * c_seg -> fp16 ----------------
__global__ __launch_bounds__(256) void ln_kernel(const float* __restrict__ x,
                                                 const float* __restrict__ gamma,
                                                 const float* __restrict__ beta) {
    int m = blockIdx.x;
    const float* xr = x + m * DIMC;
    float s = 0.f, s2 = 0.f;
    for (int d = threadIdx.x; d < DIMC; d += 256) {
        float v = xr[d];
        s += v;
        s2 += v * v;
    }
    #pragma unroll
    for (int o = 16; o; o >>= 1) {
        s += __shfl_down_sync(0xffffffffu, s, o);
        s2 += __shfl_down_sync(0xffffffffu, s2, o);
    }
    __shared__ float sh[16];
    int w = threadIdx.x >> 5, lane = threadIdx.x & 31;
    if (lane == 0) { sh[w] = s; sh[8 + w] = s2; }
    __syncthreads();
    if (threadIdx.x == 0) {
        float ts = 0.f, ts2 = 0.f;
        #pragma unroll
        for (int i = 0; i < 8; i++) { ts += sh[i]; ts2 += sh[8 + i]; }
        float mu = ts * (1.f / 768.f);
        float var = ts2 * (1.f / 768.f) - mu * mu;
        sh[0] = mu;
        sh[1] = rsqrtf(var + 1e-6f);
    }
    __syncthreads();
    float mu = sh[0], rstd = sh[1];
    float c0 = g_cS[m * 8 + 0], c1 = g_cS[m * 8 + 1], c2 = g_cS[m * 8 + 2], c3 = g_cS[m * 8 + 3];
    for (int d = threadIdx.x; d < DIMC; d += 256) {
        float c = (d < 96) ? c0 : (d < 192) ? c1 : (d < 384) ? c2 : c3;
        g_yph[m * DIMC + d] = __float2half_rn(((xr[d] - mu) * rstd * gamma[d] + beta[d]) * c);
    }
}

// ---------------- fp32 -> fp16 weight conversion ----------------
__global__ void h_cvt_kernel(const float* __restrict__ src, __half* __restrict__ dst, int n4) {
    int i = blockIdx.x * blockDim.x + threadIdx.x;
    if (i >= n4) return;
    float4 v = ((const float4*)src)[i];
    __half2 h01 = __floats2half2_rn(v.x, v.y);
    __half2 h23 = __floats2half2_rn(v.z, v.w);
    ((__half2*)dst)[i * 2] = h01;
    ((__half2*)dst)[i * 2 + 1] = h23;
}

// ================= HMMA helpers (sm_80+, family-portable) =================
__device__ __forceinline__ void ldsm_x4(uint32_t& r0, uint32_t& r1, uint32_t& r2, uint32_t& r3, uint32_t addr) {
    asm volatile("ldmatrix.sync.aligned.m8n8.x4.shared.b16 {%0,%1,%2,%3}, [%4];"
                 : "=r"(r0), "=r"(r1), "=r"(r2), "=r"(r3) : "r"(addr));
}
__device__ __forceinline__ void ldsm_x2(uint32_t& r0, uint32_t& r1, uint32_t addr) {
    asm volatile("ldmatrix.sync.aligned.m8n8.x2.shared.b16 {%0,%1}, [%2];"
                 : "=r"(r0), "=r"(r1) : "r"(addr));
}
__device__ __forceinline__ void ldsm_x2_trans(uint32_t& r0, uint32_t& r1, uint32_t addr) {
    asm volatile("ldmatrix.sync.aligned.m8n8.x2.trans.shared.b16 {%0,%1}, [%2];"
                 : "=r"(r0), "=r"(r1) : "r"(addr));
}
__device__ __forceinline__ void mma16816(float* c, const uint32_t* a, const uint32_t* b) {
    asm volatile("mma.sync.aligned.m16n8k16.row.col.f32.f16.f16.f32 "
                 "{%0,%1,%2,%3}, {%4,%5,%6,%7}, {%8,%9}, {%0,%1,%2,%3};"
                 : "+f"(c[0]), "+f"(c[1]), "+f"(c[2]), "+f"(c[3])
                 : "r"(a[0]), "r"(a[1]), "r"(a[2]), "r"(a[3]), "r"(b[0]), "r"(b[1]));
}
__device__ __forceinline__ uint32_t packh2(float a, float b) {
    __half2 h = __floats2half2_rn(a, b);
    return *(uint32_t*)&h;
}

// ================ HMMA GEMM: D[m,n] = sum_k A[m,k] * W[n,k] ================
template <int MODE>
__global__ __launch_bounds__(256) void gemm_mma(const __half* __restrict__ Wh,
                                                const float* __restrict__ bias) {
    constexpr int KDIM = (MODE == 1) ? DIMC : FC2IN;
    constexpr int NT = KDIM / 32;
    const __half* __restrict__ A = (MODE == 1) ? (const __half*)g_yph : (const __half*)g_y2h;

    __shared__ __half As[2][128][40];
    __shared__ __half Bs[2][128][40];

    int tid = threadIdx.x, wid = tid >> 5, lane = tid & 31;
    int m0 = blockIdx.y * 128, n0 = blockIdx.x * 128;
    int wm = wid & 1, wn = wid >> 1;

    int lrow = tid >> 1, lcol = (tid & 1) * 16;
    const __half* Ag = A + (m0 + lrow) * KDIM + lcol;
    const __half* Bg = Wh + (n0 + lrow) * KDIM + lcol;

    uint4 pa0 = *(const uint4*)Ag;
    uint4 pa1 = *(const uint4*)(Ag + 8);
    uint4 pb0 = *(const uint4*)Bg;
    uint4 pb1 = *(const uint4*)(Bg + 8);

    float acc[4][4][4];
    #pragma unroll
    for (int i = 0; i < 4; i++)
        #pragma unroll
        for (int j = 0; j < 4; j++)
            #pragma unroll
            for (int t = 0; t < 4; t++) acc[i][j][t] = 0.f;

    uint32_t as_base = (uint32_t)__cvta_generic_to_shared(&As[0][0][0]);
    uint32_t bs_base = (uint32_t)__cvta_generic_to_shared(&Bs[0][0][0]);
    constexpr uint32_t BUFB = 128 * 40 * 2;

    for (int kt = 0; kt < NT; kt++) {
        int buf = kt & 1;
        *(uint4*)&As[buf][lrow][lcol] = pa0;
        *(uint4*)&As[buf][lrow][lcol + 8] = pa1;
        *(uint4*)&Bs[buf][lrow][lcol] = pb0;
        *(uint4*)&Bs[buf][lrow][lcol + 8] = pb1;
        __syncthreads();
        if (kt + 1 < NT) {
            const __half* an = Ag + (kt + 1) * 32;
            const __half* bn = Bg + (kt + 1) * 32;
            pa0 = *(const uint4*)an;
            pa1 = *(const uint4*)(an + 8);
            pb0 = *(const uint4*)bn;
            pb1 = *(const uint4*)(bn + 8);
        }
        uint32_t abase = as_base + buf * BUFB;
        uint32_t bbase = bs_base + buf * BUFB;
        #pragma unroll
        for (int ks = 0; ks < 2; ks++) {
            uint32_t af[4][4];
            #pragma unroll
            for (int i = 0; i < 4; i++) {
                uint32_t r = wm * 64 + i * 16 + (lane & 15);
                uint32_t c = ks * 16 + (lane >> 4) * 8;
                ldsm_x4(af[i][0], af[i][1], af[i][2], af[i][3], abase + (r * 40 + c) * 2);
            }
            uint32_t bf[4][2];
            #pragma unroll
            for (int j = 0; j < 4; j++) {
                uint32_t r = wn * 32 + j * 8 + (lane & 7);
                uint32_t c = ks * 16 + ((lane >> 3) & 1) * 8;
                ldsm_x2(bf[j][0], bf[j][1], bbase + (r * 40 + c) * 2);
            }
            #pragma unroll
            for (int i = 0; i < 4; i++)
                #pragma unroll
                for (int j = 0; j < 4; j++) mma16816(acc[i][j], af[i], bf[j]);
        }
    }

    #pragma unroll
    for (int i = 0; i < 4; i++) {
        int m_a = m0 + wm * 64 + i * 16 + (lane >> 2);
        int m_b = m_a + 8;
        if (MODE == 1) {
            float c0a = g_cS[m_a * 8], c0b = g_cS[m_b * 8];
            #pragma unroll
            for (int j = 0; j < 4; j++) {
                int f = n0 + wn * 32 + j * 8 + (lane & 3) * 2;
                float b0v = bias[f], b1v = bias[f + 1];
                float v0 = acc[i][j][0] + c0a * b0v;
                float v1 = acc[i][j][1] + c0a * b1v;
                float v2 = acc[i][j][2] + c0b * b0v;
                float v3 = acc[i][j][3] + c0b * b1v;
                if (f < MLPH) {
                    const float is2 = 0.70710678118654752f;
                    v0 = 0.5f * v0 * (1.f + erff(v0 * is2));
                    v1 = 0.5f * v1 * (1.f + erff(v1 * is2));
                    v2 = 0.5f * v2 * (1.f + erff(v2 * is2));
                    v3 = 0.5f * v3 * (1.f + erff(v3 * is2));
                    *(__half2*)&g_y2h[(size_t)m_a * FC2IN + f] = __floats2half2_rn(v0, v1);
                    *(__half2*)&g_y2h[(size_t)m_b * FC2IN + f] = __floats2half2_rn(v2, v3);
                } else {
                    int fq = f - MLPH;
                    float sc = (fq < 768) ? 0.125f : 1.f;   // pre-scale q by 1/sqrt(64)
                    *(__half2*)&g_qkvh[(size_t)m_a * QKVD + fq] = __floats2half2_rn(v0 * sc, v1 * sc);
                    *(__half2*)&g_qkvh[(size_t)m_b * QKVD + fq] = __floats2half2_rn(v2 * sc, v3 * sc);
                }
            }
        } else {
            #pragma unroll
            for (int j = 0; j < 4; j++) {
                int o = n0 + wn * 32 + j * 8 + (lane & 3) * 2;
                int op = (o >= 768) ? (o - 768) : o;
                int seg = (op >= 384) ? 3 : (op >= 192) ? 2 : (op >= 96) ? 1 : 0;
                float Sa = g_cS[m_a * 8 + 4 + seg], Sb = g_cS[m_b * 8 + 4 + seg];
                float b0v = bias[o], b1v = bias[o + 1];
                *(float2*)&g_z[m_a * FC2OUT + o] =
                    make_float2((acc[i][j][0] + b0v) * Sa, (acc[i][j][1] + b1v) * Sa);
                *(float2*)&g_z[m_b * FC2OUT + o] =
                    make_float2((acc[i][j][2] + b0v) * Sb, (acc[i][j][3] + b1v) * Sb);
            }
        }
    }
}

// ---------------- K6: flash attention on HMMA ----------------
// grid: (96 = b*12+h, 16 = q-tiles of 64), block 128 (4 warps x 16 q rows)
__global__ __launch_bounds__(128) void fattn_kernel() {
    __shared__ __half Qs[64][72];
    __shared__ __half Ks[64][72];
    __shared__ __half Vs[64][72];
    int bh = blockIdx.x;
    int b = bh / 12, h = bh % 12;
    int q0 = blockIdx.y * 64;
    int tid = threadIdx.x, wid = tid >> 5, lane = tid & 31;
    const __half* base = g_qkvh + (size_t)b * 1024 * QKVD + h * 64;

    // load Q tile (64 x 64)
    #pragma unroll
    for (int i = 0; i < 4; i++) {
        int chunk = i * 128 + tid;
        int r = chunk >> 3, c8 = (chunk & 7) * 8;
        *(uint4*)&Qs[r][c8] = *(const uint4*)(base + (size_t)(q0 + r) * QKVD + c8);
    }
    __syncthreads();

    uint32_t qbase = (uint32_t)__cvta_generic_to_shared(&Qs[0][0]);
    uint32_t kbase = (uint32_t)__cvta_generic_to_shared(&Ks[0][0]);
    uint32_t vbase = (uint32_t)__cvta_generic_to_shared(&Vs[0][0]);

    uint32_t qf[4][4];
    #pragma unroll
    for (int kk = 0; kk < 4; kk++) {
        uint32_t addr = qbase + (((uint32_t)(wid * 16 + (lane & 15))) * 72 + kk * 16 + (lane >> 4) * 8) * 2;
        ldsm_x4(qf[kk][0], qf[kk][1], qf[kk][2], qf[kk][3], addr);
    }

    float m0 = -1e30f, m1 = -1e30f, l0 = 0.f, l1 = 0.f;
    float o[8][4];
    #pragma unroll
    for (int dj = 0; dj < 8; dj++)
        #pragma unroll
        for (int t = 0; t < 4; t++) o[dj][t] = 0.f;

    for (int kt = 0; kt < 16; kt++) {
        __syncthreads();
        #pragma unroll
        for (int i = 0; i < 4; i++) {
            int chunk = i * 128 + tid;
            int r = chunk >> 3, c8 = (chunk & 7) * 8;
            const __half* rowp = base + (size_t)(kt * 64 + r) * QKVD + c8;
            *(uint4*)&Ks[r][c8] = *(const uint4*)(rowp + 768);
            *(uint4*)&Vs[r][c8] = *(const uint4*)(rowp + 1536);
        }
        __syncthreads();

        // S = Q K^T  (16x64 per warp)
        float s[8][4];
        #pragma unroll
        for (int j = 0; j < 8; j++)
            #pragma unroll
            for (int t = 0; t < 4; t++) s[j][t] = 0.f;
        #pragma unroll
        for (int kk = 0; kk < 4; kk++) {
            #pragma unroll
            for (int j = 0; j < 8; j++) {
                uint32_t bf[2];
                uint32_t addr = kbase + (((uint32_t)(j * 8 + (lane & 7))) * 72 + kk * 16 + ((lane >> 3) & 1) * 8) * 2;
                ldsm_x2(bf[0], bf[1], addr);
                mma16816(s[j], qf[kk], bf);
            }
        }

        // online softmax (rows r0 = lane>>2, r1 = r0+8; quad lanes cover cols)
        float tm0 = -1e30f, tm1 = -1e30f;
        #pragma unroll
        for (int j = 0; j < 8; j++) {
            tm0 = fmaxf(tm0, fmaxf(s[j][0], s[j][1]));
            tm1 = fmaxf(tm1, fmaxf(s[j][2], s[j][3]));
        }
        tm0 = fmaxf(tm0, __shfl_xor_sync(0xffffffffu, tm0, 1));
        tm0 = fmaxf(tm0, __shfl_xor_sync(0xffffffffu, tm0, 2));
        tm1 = fmaxf(tm1, __shfl_xor_sync(0xffffffffu, tm1, 1));
        tm1 = fmaxf(tm1, __shfl_xor_sync(0xffffffffu, tm1, 2));
        float nm0 = fmaxf(m0, tm0), nm1 = fmaxf(m1, tm1);
        float corr0 = __expf(m0 - nm0), corr1 = __expf(m1 - nm1);
        m0 = nm0; m1 = nm1;

        uint32_t plo[8], phi[8];
        float ps0 = 0.f, ps1 = 0.f;
        #pragma unroll
        for (int j = 0; j < 8; j++) {
            float p0 = __expf(s[j][0] - m0), p1 = __expf(s[j][1] - m0);
            float p2 = __expf(s[j][2] - m1), p3 = __expf(s[j][3] - m1);
            ps0 += p0 + p1; ps1 += p2 + p3;
            plo[j] = packh2(p0, p1);
            phi[j] = packh2(p2, p3);
        }
        l0 = l0 * corr0 + ps0;
        l1 = l1 * corr1 + ps1;
        #pragma unroll
        for (int dj = 0; dj < 8; dj++) {
            o[dj][0] *= corr0; o[dj][1] *= corr0;
            o[dj][2] *= corr1; o[dj][3] *= corr1;
        }

        // O += P V   (P frags reuse S accumulator layout; V via trans ldmatrix)
        #pragma unroll
        for (int jj = 0; jj < 4; jj++) {
            uint32_t a[4] = {plo[2 * jj], phi[2 * jj], plo[2 * jj + 1], phi[2 * jj + 1]};
            #pragma unroll
            for (int dj = 0; dj < 8; dj++) {
                uint32_t bf[2];
                uint32_t addr = vbase + (((uint32_t)(jj * 16 + (lane & 15))) * 72 + dj * 8) * 2;
                ldsm_x2_trans(bf[0], bf[1], addr);
                mma16816(o[dj], a, bf);
            }
        }
    }

    // finalize: reduce l across quad, divide, store fp16
    l0 += __shfl_xor_sync(0xffffffffu, l0, 1);
    l0 += __shfl_xor_sync(0xffffffffu, l0, 2);
    l1 += __shfl_xor_sync(0xffffffffu, l1, 1);
    l1 += __shfl_xor_sync(0xffffffffu, l1, 2);
    float inv0 = 1.f / l0, inv1 = 1.f / l1;
    int r0 = q0 + wid * 16 + (lane >> 2);
    size_t m_a = (size_t)(b * 1024 + r0) * FC2IN + MLPH + h * 64;
    size_t m_b = m_a + (size_t)8 * FC2IN;
    #pragma unroll
    for (int dj = 0; dj < 8; dj++) {
        int d = dj * 8 + (lane & 3) * 2;
        *(__half2*)&g_y2h[m_a + d] = __floats2half2_rn(o[dj][0] * inv0, o[dj][1] * inv0);
        *(__half2*)&g_y2h[m_b + d] = __floats2half2_rn(o[dj][2] * inv1, o[dj][3] * inv1);
    }
}

// ---------------- K8: residual combine ----------------
__global__ void final_kernel(const float* __restrict__ x, float* __restrict__ out) {
    int i = blockIdx.x * blockDim.x + threadIdx.x;
    if (i >= NTOK * DIMC) return;
    int m = i / DIMC, c = i - m * DIMC;
    out[i] = x[i] + g_z[m * FC2OUT + c] + g_z[m * FC2OUT + 768 + c];
}

// ---------------- launch ----------------
extern "C" void kernel_launch(void* const* d_in, const int* in_sizes, int n_in,
                              void* d_out, int out_size) {
    const float* x = (const float*)d_in[0];
    const float* wr = (const float*)d_in[1];
    const float* gamma = (const float*)d_in[2];
    const float* beta = (const float*)d_in[3];
    const float* w1 = (const float*)d_in[4];
    const float* b1 = (const float*)d_in[5];
    const float* w2 = (const float*)d_in[6];
    const float* b2 = (const float*)d_in[7];
    float* out = (float*)d_out;

    __half* w1h; cudaGetSymbolAddress((void**)&w1h, g_w1h);
    __half* w2h; cudaGetSymbolAddress((void**)&w2h, g_w2h);

    router_kernel<<<NTOK / 8, 256>>>(x, wr);
    topk_kernel<<<32, 1024>>>();
    stats_kernel<<<NTOK / 256, 256>>>();
    ln_kernel<<<NTOK, 256>>>(x, gamma, beta);
    h_cvt_kernel<<<(FC1OUT * DIMC / 4 + 255) / 256, 256>>>(w1, w1h, FC1OUT * DIMC / 4);
    h_cvt_kernel<<<(FC2OUT * FC2IN / 4 + 255) / 256, 256>>>(w2, w2h, FC2OUT * FC2IN / 4);
    gemm_mma<1><<<dim3(FC1OUT / 128, NTOK / 128), 256>>>(w1h, b1);
    fattn_kernel<<<dim3(96, 16), 128>>>();
    gemm_mma<2><<<dim3(FC2OUT / 128, NTOK / 128), 256>>>(w2h, b2);
    final_kernel<<<(NTOK * DIMC + 255) / 256, 256>>>(x, out);
}

// round 5
// speedup vs baseline: 6.2221x; 1.2643x over previous
#include <cuda_runtime.h>
#include <cuda_fp16.h>
#include <math.h>
#include <cstdint>

#define NTOK 8192      // B*N = 8*1024
#define DIMC 768
#define FC1OUT 5376
#define MLPH 3072
#define QKVD 2304
#define FC2IN 3840
#define FC2OUT 1536

// ---------------- scratch (device globals; no allocation allowed) ----------------
__device__ float g_probsT[4 * NTOK];
__device__ float g_gate[4 * NTOK];
__device__ unsigned char g_sel[4 * NTOK];
__device__ float g_cS[NTOK * 8];                 // c0..c3, S0..S3 per token
__device__ __half g_yph[NTOK * DIMC];            // fp16(LN(x) * c_seg)  (fc1 A)
__device__ __half g_y2h[NTOK * FC2IN];           // fp16([gelu(mlp) | attn_out]) (fc2 A)
__device__ __half g_qkvh[NTOK * QKVD];           // fp16 qkv (q pre-scaled by 0.125)
__device__ float g_z[NTOK * FC2OUT];
__device__ __half g_w1h[FC1OUT * DIMC];          // fp16 weights
__device__ __half g_w2h[FC2OUT * FC2IN];

// ================= PTX helpers =================
__device__ __forceinline__ void cp16(uint32_t dst, const void* src) {
    asm volatile("cp.async.cg.shared.global [%0], [%1], 16;" :: "r"(dst), "l"(src));
}
__device__ __forceinline__ void cp_commit() { asm volatile("cp.async.commit_group;"); }
template <int N>
__device__ __forceinline__ void cp_wait() { asm volatile("cp.async.wait_group %0;" :: "n"(N)); }

__device__ __forceinline__ void ldsm_x4(uint32_t& r0, uint32_t& r1, uint32_t& r2, uint32_t& r3, uint32_t addr) {
    asm volatile("ldmatrix.sync.aligned.m8n8.x4.shared.b16 {%0,%1,%2,%3}, [%4];"
                 : "=r"(r0), "=r"(r1), "=r"(r2), "=r"(r3) : "r"(addr));
}
__device__ __forceinline__ void ldsm_x2(uint32_t& r0, uint32_t& r1, uint32_t addr) {
    asm volatile("ldmatrix.sync.aligned.m8n8.x2.shared.b16 {%0,%1}, [%2];"
                 : "=r"(r0), "=r"(r1) : "r"(addr));
}
__device__ __forceinline__ void ldsm_x2_trans(uint32_t& r0, uint32_t& r1, uint32_t addr) {
    asm volatile("ldmatrix.sync.aligned.m8n8.x2.trans.shared.b16 {%0,%1}, [%2];"
                 : "=r"(r0), "=r"(r1) : "r"(addr));
}
__device__ __forceinline__ void mma16816(float* c, const uint32_t* a, const uint32_t* b) {
    asm volatile("mma.sync.aligned.m16n8k16.row.col.f32.f16.f16.f32 "
                 "{%0,%1,%2,%3}, {%4,%5,%6,%7}, {%8,%9}, {%0,%1,%2,%3};"
                 : "+f"(c[0]), "+f"(c[1]), "+f"(c[2]), "+f"(c[3])
                 : "r"(a[0]), "r"(a[1]), "r"(a[2]), "r"(a[3]), "r"(b[0]), "r"(b[1]));
}
__device__ __forceinline__ uint32_t packh2(float a, float b) {
    __half2 h = __floats2half2_rn(a, b);
    return *(uint32_t*)&h;
}

// ---------------- K1: router logits + softmax (float4, warp/token) ----------------
__global__ __launch_bounds__(256) void router_kernel(const float* __restrict__ x,
                                                     const float* __restrict__ wr) {
    int warp = (blockIdx.x * blockDim.x + threadIdx.x) >> 5;
    int lane = threadIdx.x & 31;
    if (warp >= NTOK) return;
    const float4* xr = (const float4*)(x + (size_t)warp * DIMC);
    const float4* w0 = (const float4*)(wr);
    const float4* w1 = (const float4*)(wr + DIMC);
    const float4* w2 = (const float4*)(wr + 2 * DIMC);
    const float4* w3 = (const float4*)(wr + 3 * DIMC);
    float acc0 = 0.f, acc1 = 0.f, acc2 = 0.f, acc3 = 0.f;
    #pragma unroll
    for (int i = 0; i < 6; i++) {
        int idx = i * 32 + lane;
        float4 xv = xr[idx];
        float4 a = w0[idx], b = w1[idx], c = w2[idx], d = w3[idx];
        acc0 += xv.x * a.x + xv.y * a.y + xv.z * a.z + xv.w * a.w;
        acc1 += xv.x * b.x + xv.y * b.y + xv.z * b.z + xv.w * b.w;
        acc2 += xv.x * c.x + xv.y * c.y + xv.z * c.z + xv.w * c.w;
        acc3 += xv.x * d.x + xv.y * d.y + xv.z * d.z + xv.w * d.w;
    }
    #pragma unroll
    for (int o = 16; o; o >>= 1) {
        acc0 += __shfl_down_sync(0xffffffffu, acc0, o);
        acc1 += __shfl_down_sync(0xffffffffu, acc1, o);
        acc2 += __shfl_down_sync(0xffffffffu, acc2, o);
        acc3 += __shfl_down_sync(0xffffffffu, acc3, o);
    }
    if (lane == 0) {
        float mx = fmaxf(fmaxf(acc0, acc1), fmaxf(acc2, acc3));
        float p0 = expf(acc0 - mx), p1 = expf(acc1 - mx), p2 = expf(acc2 - mx), p3 = expf(acc3 - mx);
        float inv = 1.f / (p0 + p1 + p2 + p3);
        int b = warp >> 10, n = warp & 1023;
        g_probsT[(b * 4 + 0) * 1024 + n] = p0 * inv;
        g_probsT[(b * 4 + 1) * 1024 + n] = p1 * inv;
        g_probsT[(b * 4 + 2) * 1024 + n] = p2 * inv;
        g_probsT[(b * 4 + 3) * 1024 + n] = p3 * inv;
    }
}

// ---------------- K2: top-512 per (b,e) by rank counting ----------------
__global__ __launch_bounds__(1024) void topk_kernel() {
    __shared__ float sp[1024];
    int be = blockIdx.x;
    int i = threadIdx.x;
    float p = g_probsT[be * 1024 + i];
    sp[i] = p;
    __syncthreads();
    int cnt = 0;
    for (int j = 0; j < 1024; j++) {
        float q = sp[j];
        cnt += (q > p) || (q == p && j < i);
    }
    bool sel = cnt < 512;
    g_gate[be * 1024 + i] = sel ? p : 0.f;
    g_sel[be * 1024 + i] = sel ? 1 : 0;
}

// ---------------- K3: suffix counts / gate sums ----------------
__global__ void stats_kernel() {
    int m = blockIdx.x * blockDim.x + threadIdx.x;
    if (m >= NTOK) return;
    int b = m >> 10, n = m & 1023;
    float csum = 0.f, ssum = 0.f;
    float c[4], S[4];
    #pragma unroll
    for (int e = 3; e >= 0; e--) {
        csum += (float)g_sel[(b * 4 + e) * 1024 + n];
        ssum += g_gate[(b * 4 + e) * 1024 + n];
        c[e] = csum;
        S[e] = ssum;
    }
    #pragma unroll
    for (int k = 0; k < 4; k++) {
        g_cS[m * 8 + k] = c[k];
        g_cS[m * 8 + 4 + k] = S[k];
    }
}

// ---------------- K4: LayerNorm * c_seg -> fp16 (float4, warp/token) ----------------
__global__ __launch_bounds__(256) void ln_kernel(const float* __restrict__ x,
                                                 const float* __restrict__ gamma,
                                                 const float* __restrict__ beta) {
    int warp = (blockIdx.x * blockDim.x + threadIdx.x) >> 5;
    int lane = threadIdx.x & 31;
    if (warp >= NTOK) return;
    const float4* xr = (const float4*)(x + (size_t)warp * DIMC);
    float4 v[6];
    float s = 0.f, s2 = 0.f;
    #pragma unroll
    for (int i = 0; i < 6; i++) {
        v[i] = xr[i * 32 + lane];
        s += v[i].x + v[i].y + v[i].z + v[i].w;
        s2 += v[i].x * v[i].x + v[i].y * v[i].y + v[i].z * v[i].z + v[i].w * v[i].w;
    }
    #pragma unroll
    for (int o = 16; o; o >>= 1) {
        s += __shfl_xor_sync(0xffffffffu, s, o);
        s2 += __shfl_xor_sync(0xffffffffu, s2, o);
    }
    float mu = s * (1.f / 768.f);
    float var = s2 * (1.f / 768.f) - mu * mu;
    float rstd = rsqrtf(var + 1e-6f);
    float c0 = g_cS[warp * 8 + 0], c1 = g_cS[warp * 8 + 1], c2 = g_cS[warp * 8 + 2], c3 = g_cS[warp * 8 + 3];
    const float4* gm = (const float4*)gamma;
    const float4* bt = (const float4*)beta;
    #pragma unroll
    for (int i = 0; i < 6; i++) {
        int idx = i * 32 + lane;
        int d = idx * 4;
        float c = (d < 96) ? c0 : (d < 192) ? c1 : (d < 384) ? c2 : c3;
        float4 g = gm[idx], b = bt[idx];
        float r0 = ((v[i].x - mu) * rstd * g.x + b.x) * c;
        float r1 = ((v[i].y - mu) * rstd * g.y + b.y) * c;
        float r2 = ((v[i].z - mu) * rstd * g.z + b.z) * c;
        float r3 = ((v[i].w - mu) * rstd * g.w + b.w) * c;
        __half2 h0 = __floats2half2_rn(r0, r1);
        __half2 h1 = __floats2half2_rn(r2, r3);
        uint2 pk = make_uint2(*(uint32_t*)&h0, *(uint32_t*)&h1);
        *(uint2*)&g_yph[(size_t)warp * DIMC + d] = pk;
    }
}

// ---------------- fp32 -> fp16 weight conversion ----------------
__global__ void h_cvt_kernel(const float* __restrict__ src, __half* __restrict__ dst, int n4) {
    int i = blockIdx.x * blockDim.x + threadIdx.x;
    if (i >= n4) return;
    float4 v = ((const float4*)src)[i];
    __half2 h01 = __floats2half2_rn(v.x, v.y);
    __half2 h23 = __floats2half2_rn(v.z, v.w);
    ((__half2*)dst)[i * 2] = h01;
    ((__half2*)dst)[i * 2 + 1] = h23;
}

// ================ HMMA GEMM w/ cp.async 3-stage: D[m,n] = sum_k A[m,k]*W[n,k] ================
// tile M=128 N=128 BK=32; smem stage = A(128x40h) + B(128x40h) = 20480B; 3 stages = 61440B dynamic
template <int MODE>
__global__ __launch_bounds__(256) void gemm_mma(const __half* __restrict__ Wh,
                                                const float* __restrict__ bias) {
    constexpr int KDIM = (MODE == 1) ? DIMC : FC2IN;
    constexpr int NT = KDIM / 32;
    constexpr int STAGES = 3;
    constexpr uint32_t STAGE_B = 20480;
    const __half* __restrict__ A = (MODE == 1) ? (const __half*)g_yph : (const __half*)g_y2h;

    extern __shared__ char smem[];
    uint32_t sb = (uint32_t)__cvta_generic_to_shared(smem);

    int tid = threadIdx.x, wid = tid >> 5, lane = tid & 31;
    int m0 = blockIdx.y * 128, n0 = blockIdx.x * 128;
    int wm = wid & 1, wn = wid >> 1;

    // copy map: chunk c in 0..511: row=c>>2, col=(c&3)*8 halfs; this thread: chunks tid, tid+256
    int cr = tid >> 2, cc = (tid & 3) * 8;
    const __half* Ag0 = A + (size_t)(m0 + cr) * KDIM + cc;
    const __half* Ag1 = A + (size_t)(m0 + cr + 64) * KDIM + cc;
    const __half* Bg0 = Wh + (size_t)(n0 + cr) * KDIM + cc;
    const __half* Bg1 = Wh + (size_t)(n0 + cr + 64) * KDIM + cc;
    uint32_t sA0 = sb + cr * 80 + cc * 2;
    uint32_t sA1 = sb + (cr + 64) * 80 + cc * 2;
    uint32_t sB0 = sA0 + 10240;
    uint32_t sB1 = sA1 + 10240;

    float acc[4][4][4];
    #pragma unroll
    for (int i = 0; i < 4; i++)
        #pragma unroll
        for (int j = 0; j < 4; j++)
            #pragma unroll
            for (int t = 0; t < 4; t++) acc[i][j][t] = 0.f;

    // prologue: issue stages 0..STAGES-2
    #pragma unroll
    for (int s = 0; s < STAGES - 1; s++) {
        uint32_t off = s * STAGE_B;
        cp16(sA0 + off, Ag0 + s * 32);
        cp16(sA1 + off, Ag1 + s * 32);
        cp16(sB0 + off, Bg0 + s * 32);
        cp16(sB1 + off, Bg1 + s * 32);
        cp_commit();
    }

    for (int kt = 0; kt < NT; kt++) {
        cp_wait<STAGES - 2>();
        __syncthreads();
        uint32_t abase = sb + (uint32_t)(kt % STAGES) * STAGE_B;
        uint32_t bbase = abase + 10240;
        #pragma unroll
        for (int ks = 0; ks < 2; ks++) {
            uint32_t af[4][4];
            #pragma unroll
            for (int i = 0; i < 4; i++) {
                uint32_t r = wm * 64 + i * 16 + (lane & 15);
                uint32_t c = ks * 16 + (lane >> 4) * 8;
                ldsm_x4(af[i][0], af[i][1], af[i][2], af[i][3], abase + (r * 40 + c) * 2);
            }
            uint32_t bf[4][2];
            #pragma unroll
            for (int j = 0; j < 4; j++) {
                uint32_t r = wn * 32 + j * 8 + (lane & 7);
                uint32_t c = ks * 16 + ((lane >> 3) & 1) * 8;
                ldsm_x2(bf[j][0], bf[j][1], bbase + (r * 40 + c) * 2);
            }
            #pragma unroll
            for (int i = 0; i < 4; i++)
                #pragma unroll
                for (int j = 0; j < 4; j++) mma16816(acc[i][j], af[i], bf[j]);
        }
        int nk = kt + STAGES - 1;
        if (nk < NT) {
            uint32_t off = (uint32_t)(nk % STAGES) * STAGE_B;
            cp16(sA0 + off, Ag0 + nk * 32);
            cp16(sA1 + off, Ag1 + nk * 32);
            cp16(sB0 + off, Bg0 + nk * 32);
            cp16(sB1 + off, Bg1 + nk * 32);
        }
        cp_commit();
    }

    #pragma unroll
    for (int i = 0; i < 4; i++) {
        int m_a = m0 + wm * 64 + i * 16 + (lane >> 2);
        int m_b = m_a + 8;
        if (MODE == 1) {
            float c0a = g_cS[m_a * 8], c0b = g_cS[m_b * 8];
            #pragma unroll
            for (int j = 0; j < 4; j++) {
                int f = n0 + wn * 32 + j * 8 + (lane & 3) * 2;
                float b0v = bias[f], b1v = bias[f + 1];
                float v0 = acc[i][j][0] + c0a * b0v;
                float v1 = acc[i][j][1] + c0a * b1v;
                float v2 = acc[i][j][2] + c0b * b0v;
                float v3 = acc[i][j][3] + c0b * b1v;
                if (f < MLPH) {
                    const float is2 = 0.70710678118654752f;
                    v0 = 0.5f * v0 * (1.f + erff(v0 * is2));
                    v1 = 0.5f * v1 * (1.f + erff(v1 * is2));
                    v2 = 0.5f * v2 * (1.f + erff(v2 * is2));
                    v3 = 0.5f * v3 * (1.f + erff(v3 * is2));
                    *(__half2*)&g_y2h[(size_t)m_a * FC2IN + f] = __floats2half2_rn(v0, v1);
                    *(__half2*)&g_y2h[(size_t)m_b * FC2IN + f] = __floats2half2_rn(v2, v3);
                } else {
                    int fq = f - MLPH;
                    float sc = (fq < 768) ? 0.125f : 1.f;   // pre-scale q by 1/sqrt(64)
                    *(__half2*)&g_qkvh[(size_t)m_a * QKVD + fq] = __floats2half2_rn(v0 * sc, v1 * sc);
                    *(__half2*)&g_qkvh[(size_t)m_b * QKVD + fq] = __floats2half2_rn(v2 * sc, v3 * sc);
                }
            }
        } else {
            #pragma unroll
            for (int j = 0; j < 4; j++) {
                int o = n0 + wn * 32 + j * 8 + (lane & 3) * 2;
                int op = (o >= 768) ? (o - 768) : o;
                int seg = (op >= 384) ? 3 : (op >= 192) ? 2 : (op >= 96) ? 1 : 0;
                float Sa = g_cS[m_a * 8 + 4 + seg], Sb = g_cS[m_b * 8 + 4 + seg];
                float b0v = bias[o], b1v = bias[o + 1];
                *(float2*)&g_z[m_a * FC2OUT + o] =
                    make_float2((acc[i][j][0] + b0v) * Sa, (acc[i][j][1] + b1v) * Sa);
                *(float2*)&g_z[m_b * FC2OUT + o] =
                    make_float2((acc[i][j][2] + b0v) * Sb, (acc[i][j][3] + b1v) * Sb);
            }
        }
    }
}

// ---------------- K6: flash attention on HMMA ----------------
// grid: (96 = b*12+h, 8 q-tiles of 128), block 256 (8 warps x 16 q rows)
__global__ __launch_bounds__(256) void fattn_kernel() {
    __shared__ __half Qs[128][72];
    __shared__ __half Ks[64][72];
    __shared__ __half Vs[64][72];
    int bh = blockIdx.x;
    int b = bh / 12, h = bh % 12;
    int q0 = blockIdx.y * 128;
    int tid = threadIdx.x, wid = tid >> 5, lane = tid & 31;
    const __half* base = g_qkvh + (size_t)b * 1024 * QKVD + h * 64;

    // load Q tile (128 x 64)
    #pragma unroll
    for (int i = 0; i < 4; i++) {
        int chunk = i * 256 + tid;
        int r = chunk >> 3, c8 = (chunk & 7) * 8;
        *(uint4*)&Qs[r][c8] = *(const uint4*)(base + (size_t)(q0 + r) * QKVD + c8);
    }
    __syncthreads();

    uint32_t qbase = (uint32_t)__cvta_generic_to_shared(&Qs[0][0]);
    uint32_t kbase = (uint32_t)__cvta_generic_to_shared(&Ks[0][0]);
    uint32_t vbase = (uint32_t)__cvta_generic_to_shared(&Vs[0][0]);

    uint32_t qf[4][4];
    #pragma unroll
    for (int kk = 0; kk < 4; kk++) {
        uint32_t addr = qbase + (((uint32_t)(wid * 16 + (lane & 15))) * 72 + kk * 16 + (lane >> 4) * 8) * 2;
        ldsm_x4(qf[kk][0], qf[kk][1], qf[kk][2], qf[kk][3], addr);
    }

    float m0 = -1e30f, m1 = -1e30f, l0 = 0.f, l1 = 0.f;
    float o[8][4];
    #pragma unroll
    for (int dj = 0; dj < 8; dj++)
        #pragma unroll
        for (int t = 0; t < 4; t++) o[dj][t] = 0.f;

    for (int kt = 0; kt < 16; kt++) {
        __syncthreads();
        #pragma unroll
        for (int i = 0; i < 2; i++) {
            int chunk = i * 256 + tid;
            int r = chunk >> 3, c8 = (chunk & 7) * 8;
            const __half* rowp = base + (size_t)(kt * 64 + r) * QKVD + c8;
            *(uint4*)&Ks[r][c8] = *(const uint4*)(rowp + 768);
            *(uint4*)&Vs[r][c8] = *(const uint4*)(rowp + 1536);
        }
        __syncthreads();

        // S = Q K^T  (16x64 per warp)
        float s[8][4];
        #pragma unroll
        for (int j = 0; j < 8; j++)
            #pragma unroll
            for (int t = 0; t < 4; t++) s[j][t] = 0.f;
        #pragma unroll
        for (int kk = 0; kk < 4; kk++) {
            #pragma unroll
            for (int j = 0; j < 8; j++) {
                uint32_t bf[2];
                uint32_t addr = kbase + (((uint32_t)(j * 8 + (lane & 7))) * 72 + kk * 16 + ((lane >> 3) & 1) * 8) * 2;
                ldsm_x2(bf[0], bf[1], addr);
                mma16816(s[j], qf[kk], bf);
            }
        }

        // online softmax
        float tm0 = -1e30f, tm1 = -1e30f;
        #pragma unroll
        for (int j = 0; j < 8; j++) {
            tm0 = fmaxf(tm0, fmaxf(s[j][0], s[j][1]));
            tm1 = fmaxf(tm1, fmaxf(s[j][2], s[j][3]));
        }
        tm0 = fmaxf(tm0, __shfl_xor_sync(0xffffffffu, tm0, 1));
        tm0 = fmaxf(tm0, __shfl_xor_sync(0xffffffffu, tm0, 2));
        tm1 = fmaxf(tm1, __shfl_xor_sync(0xffffffffu, tm1, 1));
        tm1 = fmaxf(tm1, __shfl_xor_sync(0xffffffffu, tm1, 2));
        float nm0 = fmaxf(m0, tm0), nm1 = fmaxf(m1, tm1);
        float corr0 = __expf(m0 - nm0), corr1 = __expf(m1 - nm1);
        m0 = nm0; m1 = nm1;

        uint32_t plo[8], phi[8];
        float ps0 = 0.f, ps1 = 0.f;
        #pragma unroll
        for (int j = 0; j < 8; j++) {
            float p0 = __expf(s[j][0] - m0), p1 = __expf(s[j][1] - m0);
            float p2 = __expf(s[j][2] - m1), p3 = __expf(s[j][3] - m1);
            ps0 += p0 + p1; ps1 += p2 + p3;
            plo[j] = packh2(p0, p1);
            phi[j] = packh2(p2, p3);
        }
        l0 = l0 * corr0 + ps0;
        l1 = l1 * corr1 + ps1;
        #pragma unroll
        for (int dj = 0; dj < 8; dj++) {
            o[dj][0] *= corr0; o[dj][1] *= corr0;
            o[dj][2] *= corr1; o[dj][3] *= corr1;
        }

        // O += P V
        #pragma unroll
        for (int jj = 0; jj < 4; jj++) {
            uint32_t a[4] = {plo[2 * jj], phi[2 * jj], plo[2 * jj + 1], phi[2 * jj + 1]};
            #pragma unroll
            for (int dj = 0; dj < 8; dj++) {
                uint32_t bf[2];
                uint32_t addr = vbase + (((uint32_t)(jj * 16 + (lane & 15))) * 72 + dj * 8) * 2;
                ldsm_x2_trans(bf[0], bf[1], addr);
                mma16816(o[dj], a, bf);
            }
        }
    }

    l0 += __shfl_xor_sync(0xffffffffu, l0, 1);
    l0 += __shfl_xor_sync(0xffffffffu, l0, 2);
    l1 += __shfl_xor_sync(0xffffffffu, l1, 1);
    l1 += __shfl_xor_sync(0xffffffffu, l1, 2);
    float inv0 = 1.f / l0, inv1 = 1.f / l1;
    int r0 = q0 + wid * 16 + (lane >> 2);
    size_t m_a = (size_t)(b * 1024 + r0) * FC2IN + MLPH + h * 64;
    size_t m_b = m_a + (size_t)8 * FC2IN;
    #pragma unroll
    for (int dj = 0; dj < 8; dj++) {
        int d = dj * 8 + (lane & 3) * 2;
        *(__half2*)&g_y2h[m_a + d] = __floats2half2_rn(o[dj][0] * inv0, o[dj][1] * inv0);
        *(__half2*)&g_y2h[m_b + d] = __floats2half2_rn(o[dj][2] * inv1, o[dj][3] * inv1);
    }
}

// ---------------- K8: residual combine ----------------
__global__ void final_kernel(const float* __restrict__ x, float* __restrict__ out) {
    int i = blockIdx.x * blockDim.x + threadIdx.x;
    if (i >= NTOK * DIMC) return;
    int m = i / DIMC, c = i - m * DIMC;
    out[i] = x[i] + g_z[m * FC2OUT + c] + g_z[m * FC2OUT + 768 + c];
}

// ---------------- launch ----------------
extern "C" void kernel_launch(void* const* d_in, const int* in_sizes, int n_in,
                              void* d_out, int out_size) {
    const float* x = (const float*)d_in[0];
    const float* wr = (const float*)d_in[1];
    const float* gamma = (const float*)d_in[2];
    const float* beta = (const float*)d_in[3];
    const float* w1 = (const float*)d_in[4];
    const float* b1 = (const float*)d_in[5];
    const float* w2 = (const float*)d_in[6];
    const float* b2 = (const float*)d_in[7];
    float* out = (float*)d_out;

    cudaFuncSetAttribute(gemm_mma<1>, cudaFuncAttributeMaxDynamicSharedMemorySize, 61440);
    cudaFuncSetAttribute(gemm_mma<2>, cudaFuncAttributeMaxDynamicSharedMemorySize, 61440);

    __half* w1h; cudaGetSymbolAddress((void**)&w1h, g_w1h);
    __half* w2h; cudaGetSymbolAddress((void**)&w2h, g_w2h);

    router_kernel<<<NTOK / 8, 256>>>(x, wr);
    topk_kernel<<<32, 1024>>>();
    stats_kernel<<<NTOK / 256, 256>>>();
    ln_kernel<<<NTOK / 8, 256>>>(x, gamma, beta);
    h_cvt_kernel<<<(FC1OUT * DIMC / 4 + 255) / 256, 256>>>(w1, w1h, FC1OUT * DIMC / 4);
    h_cvt_kernel<<<(FC2OUT * FC2IN / 4 + 255) / 256, 256>>>(w2, w2h, FC2OUT * FC2IN / 4);
    gemm_mma<1><<<dim3(FC1OUT / 128, NTOK / 128), 256, 61440>>>(w1h, b1);
    fattn_kernel<<<dim3(96, 8), 256>>>();
    gemm_mma<2><<<dim3(FC2OUT / 128, NTOK / 128), 256, 61440>>>(w2h, b2);
    final_kernel<<<(NTOK * DIMC + 255) / 256, 256>>>(x, out);
}